// round 16
// baseline (speedup 1.0000x reference)
#include <cuda_runtime.h>
#include <math.h>

#define HH 256
#define WW 256
#define CC 16
#define BB 16
#define NCP 64
#define NA 67    // 64 + 3 affine
#define NW 2144  // 67 rows x 32 rhs cols
#define FUSED_BLOCKS 256   // <= 148 SMs * 2 blocks/SM (enforced by launch_bounds)

// --------------------------- device constants/scratch -----------------------
struct TpsConst {
    double inv[NA][NA];   // inverse of the constant 67x67 TPS system (host fp64)
    double wid[NA][2];    // Inv @ [cp;0]  (identity solution, host fp64 exact)
};
__device__ TpsConst d_c;
__device__ float g_ws[NCP][32];     // spline weights  [n][2b+k]
__device__ float g_vs[BB][3][2];    // affine weights  [b][p][k]
__device__ uint2 g_meta[BB][HH*WW]; // {(y0<<16)|x0, (wy<<16)|wx}  8B packed
__device__ unsigned int g_c1;       // produce counter (self-resetting)
__device__ unsigned int g_c2;       // drain counter  (self-resetting)

static TpsConst h_c;

// --------------------------- PDL primitives ---------------------------------
__device__ __forceinline__ void pdl_trigger() {
#if __CUDA_ARCH__ >= 900
    asm volatile("griddepcontrol.launch_dependents;");
#endif
}
__device__ __forceinline__ void pdl_wait() {
#if __CUDA_ARCH__ >= 900
    asm volatile("griddepcontrol.wait;" ::: "memory");
#endif
}

// --------------------------- host precompute (capture-time) -----------------
static inline float h_cp_y(int i) { return (float)(i >> 3) / 7.0f; }
static inline float h_cp_x(int i) { return (float)(i & 7) / 7.0f; }

static void host_build_const() {
    static double A[NA][2 * NA];
    for (int i = 0; i < NA; i++) {
        for (int j = 0; j < NA; j++) {
            float val;
            if (i < NCP && j < NCP) {
                float dy = h_cp_y(i) - h_cp_y(j);
                float dx = h_cp_x(i) - h_cp_x(j);
                float r2 = dy * dy + dx * dx;
                float rm = r2 > 1e-10f ? r2 : 1e-10f;
                val = 0.5f * r2 * logf(rm);
            } else if (i < NCP) {
                int p = j - NCP;
                val = (p == 0) ? h_cp_y(i) : (p == 1) ? h_cp_x(i) : 1.0f;
            } else if (j < NCP) {
                int p = i - NCP;
                val = (p == 0) ? h_cp_y(j) : (p == 1) ? h_cp_x(j) : 1.0f;
            } else {
                val = 0.0f;
            }
            A[i][j] = (double)val;
            A[i][NA + j] = (i == j) ? 1.0 : 0.0;
        }
    }
    for (int kk = 0; kk < NA; kk++) {
        int piv = kk;
        double best = fabs(A[kk][kk]);
        for (int i = kk + 1; i < NA; i++) {
            double a = fabs(A[i][kk]);
            if (a > best) { best = a; piv = i; }
        }
        if (piv != kk)
            for (int j = 0; j < 2 * NA; j++) {
                double t = A[kk][j]; A[kk][j] = A[piv][j]; A[piv][j] = t;
            }
        double ip = 1.0 / A[kk][kk];
        for (int j = 0; j < 2 * NA; j++) A[kk][j] *= ip;
        for (int i = 0; i < NA; i++) {
            if (i == kk) continue;
            double f = A[i][kk];
            if (f == 0.0) continue;
            for (int j = kk; j < 2 * NA; j++) A[i][j] -= f * A[kk][j];
        }
    }
    for (int i = 0; i < NA; i++)
        for (int j = 0; j < NA; j++)
            h_c.inv[i][j] = A[i][NA + j];
    for (int r = 0; r < NA; r++)
        for (int k = 0; k < 2; k++) {
            double s = 0.0;
            for (int i = 0; i < NCP; i++)
                s += h_c.inv[r][i] * (double)(k == 0 ? h_cp_y(i) : h_cp_x(i));
            h_c.wid[r][k] = s;
        }
}

// --------------------------- helpers -----------------------------------------
__device__ __forceinline__ float cp_yd(int i) { return __fdiv_rn((float)(i >> 3), 7.0f); }
__device__ __forceinline__ float cp_xd(int i) { return __fdiv_rn((float)(i & 7), 7.0f); }

// One weight output (row r, rhs col c) by a full warp — R8-identical arithmetic.
__device__ __forceinline__ void weight_output(int o, int lane,
                                              const float* __restrict__ off) {
    const int r = o >> 5, c = o & 31;
    const int b = c >> 1, k = c & 1;

    double acc = 0.0;
#pragma unroll
    for (int h = 0; h < 2; h++) {
        const int ii = lane + h * 32;
        const float base = (k == 0) ? cp_yd(ii) : cp_xd(ii);
        const float s  = base + __ldg(&off[(b * NCP + ii) * 2 + k]); // fp32, like ref
        const float op = s - base;                                    // effective offset
        acc += d_c.inv[r][ii] * (double)op;
    }
#pragma unroll
    for (int oo = 16; oo > 0; oo >>= 1)
        acc += __shfl_down_sync(0xffffffffu, acc, oo);

    if (lane == 0) {
        const double wv = acc + d_c.wid[r][k];
        if (r < NCP) g_ws[r][c] = (float)wv;
        else         g_vs[b][r - NCP][k] = (float)wv;
    }
}

// --------------------------- packed f32x2 helpers ---------------------------
__device__ __forceinline__ unsigned long long pack2(float v) {
    unsigned int u = __float_as_uint(v);
    unsigned long long d;
    asm("mov.b64 %0, {%1, %1};" : "=l"(d) : "r"(u));
    return d;
}
__device__ __forceinline__ void fma2(unsigned long long& d, unsigned long long a,
                                     unsigned long long b, unsigned long long c) {
    asm("fma.rn.f32x2 %0, %1, %2, %3;" : "=l"(d) : "l"(a), "l"(b), "l"(c));
}
__device__ __forceinline__ void unpack2(unsigned long long v, float& lo, float& hi) {
    unsigned int a, b;
    asm("mov.b64 {%0, %1}, %2;" : "=r"(a), "=r"(b) : "l"(v));
    lo = __uint_as_float(a); hi = __uint_as_float(b);
}

// --------------------------- kernel 0: fused weights + loc -------------------
// R9-proven shell: 256 blocks with __launch_bounds__(256, 2) -> reg cap 128,
// >=2 blocks/SM, all blocks wave-1 co-resident -> spin barrier deadlock-free.
// R15-lean body: phase B in TWO passes of 8 batches (acc[8], phi inlined) ->
// ~60 live regs, no spills (the R14 failure mode).
__global__ void __launch_bounds__(256, 2) tps_fused_kernel(const float* __restrict__ off) {
    pdl_trigger();   // let tps_sample_kernel launch and park at its wait

    const int tid  = threadIdx.x;
    const int wid  = tid >> 5;
    const int lane = tid & 31;

    // ---- phase A: this block's weight outputs ----
    {
        const int g = blockIdx.x * 8 + wid;          // 0..2047
        weight_output(g, lane, off);
        if (g < NW - 2048) weight_output(2048 + g, lane, off);
        __syncthreads();
        if (tid == 0) {
            __threadfence();
            atomicAdd(&g_c1, 1u);
        }
    }

    // ---- barrier: wait for all blocks, then self-reset for next replay ----
    if (tid == 0) {
        volatile unsigned int* p = &g_c1;
        while (*p < (unsigned)FUSED_BLOCKS) { }
        __threadfence();
        unsigned t2 = atomicAdd(&g_c2, 1u);
        if (t2 == (unsigned)FUSED_BLOCKS - 1u) {
            g_c1 = 0u;
            g_c2 = 0u;
            __threadfence();
        }
    }
    __syncthreads();

    // ---- phase B: warp-field evaluation, two passes of 8 batches ----
    __shared__ float ws[NCP][32];
    __shared__ float vs[BB][3][2];
    for (int e = tid; e < NCP * 32; e += 256) (&ws[0][0])[e] = (&g_ws[0][0])[e];
    if (tid < BB * 3 * 2) (&vs[0][0][0])[tid] = (&g_vs[0][0][0])[tid];
    __syncthreads();

    const int m  = blockIdx.x * 256 + tid;
    const int iy = m >> 8, ix = m & 255;
    const float qy = __fdiv_rn((float)iy, 255.0f);
    const float qx = __fdiv_rn((float)ix, 255.0f);
    const unsigned long long qy2 = pack2(qy), qx2 = pack2(qx), one2 = pack2(1.0f);

#pragma unroll
    for (int p = 0; p < 2; p++) {          // batch halves: p*8 .. p*8+7
        unsigned long long acc[8];
#pragma unroll
        for (int j = 0; j < 8; j++) acc[j] = 0ull;

#pragma unroll
        for (int oy = 0; oy < 8; oy++) {
            const float dy = qy - (float)oy / 7.0f;   // folds at compile time
            const float dyy = dy * dy;
#pragma unroll
            for (int ox = 0; ox < 8; ox++) {
                const float dx = qx - (float)ox / 7.0f;
                const float r2 = dx * dx + dyy;
                const float phi = 0.5f * r2 * __logf(fmaxf(r2, 1e-10f));
                const unsigned long long phi2 = pack2(phi);
                const ulonglong2* wp =
                    (const ulonglong2*)&ws[oy * 8 + ox][p * 16];
#pragma unroll
                for (int g = 0; g < 4; g++) {
                    ulonglong2 w2 = wp[g];   // LDS.128 broadcast: two (y,x) pairs
                    fma2(acc[2 * g],     phi2, w2.x, acc[2 * g]);
                    fma2(acc[2 * g + 1], phi2, w2.y, acc[2 * g + 1]);
                }
            }
        }

#pragma unroll
        for (int j = 0; j < 8; j++) {
            const int b = p * 8 + j;
            unsigned long long v0 = *(const unsigned long long*)&vs[b][0][0];
            unsigned long long v1 = *(const unsigned long long*)&vs[b][1][0];
            unsigned long long v2 = *(const unsigned long long*)&vs[b][2][0];
            fma2(acc[j], one2, v2, acc[j]);
            fma2(acc[j], qy2,  v0, acc[j]);
            fma2(acc[j], qx2,  v1, acc[j]);

            float ly, lx;
            unpack2(acc[j], ly, lx);
            const float xf = lx * 255.0f;   // loc[...,1] * (W-1)
            const float yf = ly * 255.0f;   // loc[...,0] * (H-1)
            const float x0f = floorf(xf), y0f = floorf(yf);
            const int x0 = (int)x0f, y0 = (int)y0f;           // |x0| << 32767
            const float wx = xf - x0f, wy = yf - y0f;          // in [0,1)
            uint2 mt;
            mt.x = ((unsigned)x0 & 0xffffu) | ((unsigned)y0 << 16);
            mt.y = __float2uint_rn(wx * 65535.0f) |
                   (__float2uint_rn(wy * 65535.0f) << 16);
            g_meta[b][m] = mt;
        }
    }
}

// --------------------------- kernel 1: bilinear gather ----------------------
// R8-exact: thread per (b, pixel, channel-quad). PDL secondary of fused.
__global__ void __launch_bounds__(256) tps_sample_kernel(
    const float* __restrict__ vol, float* __restrict__ out) {
    const int idx = blockIdx.x * 256 + threadIdx.x;
    const int c4 = idx & 3;
    const int m  = (idx >> 2) & (HH * WW - 1);
    const int b  = idx >> 18;

    pdl_wait();   // g_meta now visible

    const uint2 mt = __ldg(&g_meta[b][m]);
    const int x0 = (int)(short)(mt.x & 0xffffu);
    const int y0 = (int)(short)(mt.x >> 16);
    const float wx = (float)(mt.y & 0xffffu) * (1.0f / 65535.0f);
    const float wy = (float)(mt.y >> 16)     * (1.0f / 65535.0f);
    const int x1 = x0 + 1, y1 = y0 + 1;

    const float fy0 = ((unsigned)y0 < HH) ? 1.0f : 0.0f;
    const float fy1 = ((unsigned)y1 < HH) ? 1.0f : 0.0f;
    const float fx0 = ((unsigned)x0 < WW) ? 1.0f : 0.0f;
    const float fx1 = ((unsigned)x1 < WW) ? 1.0f : 0.0f;

    const int xc0 = min(max(x0, 0), WW - 1);
    const int xc1 = min(max(x1, 0), WW - 1);
    const int yc0 = min(max(y0, 0), HH - 1);
    const int yc1 = min(max(y1, 0), HH - 1);

    const float4* __restrict__ vf = (const float4*)vol;
    const int base = b << 16;
    float4 v00 = __ldg(&vf[(base + yc0 * WW + xc0) * 4 + c4]);
    float4 v01 = __ldg(&vf[(base + yc0 * WW + xc1) * 4 + c4]);
    float4 v10 = __ldg(&vf[(base + yc1 * WW + xc0) * 4 + c4]);
    float4 v11 = __ldg(&vf[(base + yc1 * WW + xc1) * 4 + c4]);

    const float w00 = (1.0f - wy) * (1.0f - wx) * (fy0 * fx0);
    const float w01 = (1.0f - wy) * wx          * (fy0 * fx1);
    const float w10 = wy * (1.0f - wx)          * (fy1 * fx0);
    const float w11 = wy * wx                   * (fy1 * fx1);

    float4 r;
    r.x = v00.x * w00 + v01.x * w01 + v10.x * w10 + v11.x * w11;
    r.y = v00.y * w00 + v01.y * w01 + v10.y * w10 + v11.y * w11;
    r.z = v00.z * w00 + v01.z * w01 + v10.z * w10 + v11.z * w11;
    r.w = v00.w * w00 + v01.w * w01 + v10.w * w10 + v11.w * w11;
    ((float4*)out)[idx] = r;
}

// --------------------------- launch ------------------------------------------
extern "C" void kernel_launch(void* const* d_in, const int* in_sizes, int n_in,
                              void* d_out, int out_size) {
    const float* vol        = (const float*)d_in[0];
    const float* cp_offsets = (const float*)d_in[1];
    float* out = (float*)d_out;

    host_build_const();   // pure host math; recorded copy node only
    cudaMemcpyToSymbolAsync(d_c, &h_c, sizeof(h_c), 0,
                            cudaMemcpyHostToDevice, 0);

    // fused weights + loc: 256 blocks, guaranteed >=2 blocks/SM co-residency
    tps_fused_kernel<<<FUSED_BLOCKS, 256>>>(cp_offsets);

    // sample: PDL secondary of fused
    {
        cudaLaunchConfig_t cfg = {};
        cfg.gridDim  = dim3((BB * HH * WW * 4) / 256);
        cfg.blockDim = dim3(256);
        cudaLaunchAttribute attr[1];
        attr[0].id = cudaLaunchAttributeProgrammaticStreamSerialization;
        attr[0].val.programmaticStreamSerializationAllowed = 1;
        cfg.attrs = attr;
        cfg.numAttrs = 1;
        cudaLaunchKernelEx(&cfg, tps_sample_kernel, vol, out);
    }
}

// round 17
// speedup vs baseline: 1.0808x; 1.0808x over previous
#include <cuda_runtime.h>
#include <math.h>

#define HH 256
#define WW 256
#define CC 16
#define BB 16
#define NCP 64
#define NA 67   // 64 + 3 affine

// --------------------------- device constants/scratch -----------------------
struct TpsConst {
    double inv[NA][NA];   // inverse of the constant 67x67 TPS system (host fp64)
    double wid[NA][2];    // Inv @ [cp;0]  (identity solution, host fp64 exact)
};
__device__ TpsConst d_c;
__device__ float g_ws[NCP][32];     // spline weights  [n][2b+k]
__device__ float g_vs[BB][3][2];    // affine weights  [b][p][k]
__device__ uint2 g_meta[BB][HH*WW]; // {(y0<<16)|x0, (wy<<16)|wx}  8B packed

static TpsConst h_c;

// --------------------------- PDL primitives ---------------------------------
__device__ __forceinline__ void pdl_trigger() {
#if __CUDA_ARCH__ >= 900
    asm volatile("griddepcontrol.launch_dependents;");
#endif
}
__device__ __forceinline__ void pdl_wait() {
#if __CUDA_ARCH__ >= 900
    asm volatile("griddepcontrol.wait;" ::: "memory");
#endif
}

// --------------------------- host precompute (capture-time) -----------------
static inline float h_cp_y(int i) { return (float)(i >> 3) / 7.0f; }
static inline float h_cp_x(int i) { return (float)(i & 7) / 7.0f; }

static void host_build_const() {
    static double A[NA][2 * NA];
    for (int i = 0; i < NA; i++) {
        for (int j = 0; j < NA; j++) {
            float val;
            if (i < NCP && j < NCP) {
                float dy = h_cp_y(i) - h_cp_y(j);
                float dx = h_cp_x(i) - h_cp_x(j);
                float r2 = dy * dy + dx * dx;
                float rm = r2 > 1e-10f ? r2 : 1e-10f;
                val = 0.5f * r2 * logf(rm);
            } else if (i < NCP) {
                int p = j - NCP;
                val = (p == 0) ? h_cp_y(i) : (p == 1) ? h_cp_x(i) : 1.0f;
            } else if (j < NCP) {
                int p = i - NCP;
                val = (p == 0) ? h_cp_y(j) : (p == 1) ? h_cp_x(j) : 1.0f;
            } else {
                val = 0.0f;
            }
            A[i][j] = (double)val;
            A[i][NA + j] = (i == j) ? 1.0 : 0.0;
        }
    }
    for (int kk = 0; kk < NA; kk++) {
        int piv = kk;
        double best = fabs(A[kk][kk]);
        for (int i = kk + 1; i < NA; i++) {
            double a = fabs(A[i][kk]);
            if (a > best) { best = a; piv = i; }
        }
        if (piv != kk)
            for (int j = 0; j < 2 * NA; j++) {
                double t = A[kk][j]; A[kk][j] = A[piv][j]; A[piv][j] = t;
            }
        double ip = 1.0 / A[kk][kk];
        for (int j = 0; j < 2 * NA; j++) A[kk][j] *= ip;
        for (int i = 0; i < NA; i++) {
            if (i == kk) continue;
            double f = A[i][kk];
            if (f == 0.0) continue;
            for (int j = kk; j < 2 * NA; j++) A[i][j] -= f * A[kk][j];
        }
    }
    for (int i = 0; i < NA; i++)
        for (int j = 0; j < NA; j++)
            h_c.inv[i][j] = A[i][NA + j];
    for (int r = 0; r < NA; r++)
        for (int k = 0; k < 2; k++) {
            double s = 0.0;
            for (int i = 0; i < NCP; i++)
                s += h_c.inv[r][i] * (double)(k == 0 ? h_cp_y(i) : h_cp_x(i));
            h_c.wid[r][k] = s;
        }
}

// --------------------------- kernel 0: apply inverse (warp per output) ------
__device__ __forceinline__ float cp_yd(int i) { return __fdiv_rn((float)(i >> 3), 7.0f); }
__device__ __forceinline__ float cp_xd(int i) { return __fdiv_rn((float)(i & 7), 7.0f); }

__global__ void __launch_bounds__(256) tps_apply_kernel(const float* __restrict__ off) {
    pdl_trigger();

    const int w    = (blockIdx.x * 256 + threadIdx.x) >> 5;  // output id 0..2143
    const int lane = threadIdx.x & 31;
    const int r = w >> 5, c = w & 31;   // solution row, rhs column
    const int b = c >> 1, k = c & 1;

    double acc = 0.0;
#pragma unroll
    for (int h = 0; h < 2; h++) {
        const int ii = lane + h * 32;
        const float base = (k == 0) ? cp_yd(ii) : cp_xd(ii);
        const float s  = base + __ldg(&off[(b * NCP + ii) * 2 + k]); // fp32, like ref
        const float op = s - base;                                    // effective offset
        acc += d_c.inv[r][ii] * (double)op;
    }
#pragma unroll
    for (int o = 16; o > 0; o >>= 1)
        acc += __shfl_down_sync(0xffffffffu, acc, o);

    if (lane == 0) {
        const double wv = acc + d_c.wid[r][k];
        if (r < NCP) g_ws[r][c] = (float)wv;
        else         g_vs[b][r - NCP][k] = (float)wv;
    }
}

// --------------------------- packed f32x2 helpers ---------------------------
__device__ __forceinline__ unsigned long long pack2(float v) {
    unsigned int u = __float_as_uint(v);
    unsigned long long d;
    asm("mov.b64 %0, {%1, %1};" : "=l"(d) : "r"(u));
    return d;
}
__device__ __forceinline__ void fma2(unsigned long long& d, unsigned long long a,
                                     unsigned long long b, unsigned long long c) {
    asm("fma.rn.f32x2 %0, %1, %2, %3;" : "=l"(d) : "l"(a), "l"(b), "l"(c));
}
__device__ __forceinline__ void unpack2(unsigned long long v, float& lo, float& hi) {
    unsigned int a, b;
    asm("mov.b64 {%0, %1}, %2;" : "=r"(a), "=r"(b) : "l"(v));
    lo = __uint_as_float(a); hi = __uint_as_float(b);
}

// --------------------------- kernel 1: loc (warp field) ---------------------
// Two threads per pixel, 8 batches each (R10-validated arithmetic): 4096
// warps (28/SM), half the acc dependency chain, double latency cover.
__global__ void __launch_bounds__(256) tps_loc_kernel() {
    pdl_trigger();   // let tps_sample_kernel launch and park at its wait

    const int tid  = threadIdx.x;
    const int t    = blockIdx.x * 256 + tid;
    const int m    = t >> 1;
    const int half = t & 1;            // batches half*8 .. half*8+7
    const int iy = m >> 8, ix = m & 255;
    const float qy = __fdiv_rn((float)iy, 255.0f);
    const float qx = __fdiv_rn((float)ix, 255.0f);

    pdl_wait();   // apply's g_ws/g_vs now visible

    __shared__ float ws[NCP][32];
    __shared__ float vs[BB][3][2];
    for (int e = tid; e < NCP * 32; e += 256) (&ws[0][0])[e] = (&g_ws[0][0])[e];
    if (tid < BB * 3 * 2) (&vs[0][0][0])[tid] = (&g_vs[0][0][0])[tid];
    __syncthreads();

    unsigned long long acc[8];
#pragma unroll
    for (int j = 0; j < 8; j++) acc[j] = 0ull;

#pragma unroll
    for (int oy = 0; oy < 8; oy++) {
        const float dy = qy - (float)oy / 7.0f;   // folds at compile time
        const float dyy = dy * dy;
#pragma unroll
        for (int ox = 0; ox < 8; ox++) {
            const float dx = qx - (float)ox / 7.0f;
            const float r2 = dx * dx + dyy;
            const float phi = 0.5f * r2 * __logf(fmaxf(r2, 1e-10f));
            const unsigned long long phi2 = pack2(phi);
            const ulonglong2* wp =
                (const ulonglong2*)&ws[oy * 8 + ox][half * 16];
#pragma unroll
            for (int g = 0; g < 4; g++) {
                ulonglong2 w2 = wp[g];   // LDS.128: two (y,x) pairs
                fma2(acc[2 * g],     phi2, w2.x, acc[2 * g]);
                fma2(acc[2 * g + 1], phi2, w2.y, acc[2 * g + 1]);
            }
        }
    }

    const unsigned long long qy2 = pack2(qy), qx2 = pack2(qx), one2 = pack2(1.0f);
#pragma unroll
    for (int j = 0; j < 8; j++) {
        const int b = half * 8 + j;
        unsigned long long v0 = *(const unsigned long long*)&vs[b][0][0];
        unsigned long long v1 = *(const unsigned long long*)&vs[b][1][0];
        unsigned long long v2 = *(const unsigned long long*)&vs[b][2][0];
        fma2(acc[j], one2, v2, acc[j]);
        fma2(acc[j], qy2,  v0, acc[j]);
        fma2(acc[j], qx2,  v1, acc[j]);

        float ly, lx;
        unpack2(acc[j], ly, lx);
        const float xf = lx * 255.0f;   // loc[...,1] * (W-1)
        const float yf = ly * 255.0f;   // loc[...,0] * (H-1)
        const float x0f = floorf(xf), y0f = floorf(yf);
        const int x0 = (int)x0f, y0 = (int)y0f;           // |x0| << 32767
        const float wx = xf - x0f, wy = yf - y0f;          // in [0,1)
        uint2 mt;
        mt.x = ((unsigned)x0 & 0xffffu) | ((unsigned)y0 << 16);
        mt.y = __float2uint_rn(wx * 65535.0f) |
               (__float2uint_rn(wy * 65535.0f) << 16);
        g_meta[b][m] = mt;
    }
}

// --------------------------- kernel 2: bilinear gather ----------------------
// R8-exact: thread per (b, pixel, channel-quad). PDL secondary of loc.
__global__ void __launch_bounds__(256) tps_sample_kernel(
    const float* __restrict__ vol, float* __restrict__ out) {
    const int idx = blockIdx.x * 256 + threadIdx.x;
    const int c4 = idx & 3;
    const int m  = (idx >> 2) & (HH * WW - 1);
    const int b  = idx >> 18;

    pdl_wait();   // g_meta now visible

    const uint2 mt = __ldg(&g_meta[b][m]);
    const int x0 = (int)(short)(mt.x & 0xffffu);
    const int y0 = (int)(short)(mt.x >> 16);
    const float wx = (float)(mt.y & 0xffffu) * (1.0f / 65535.0f);
    const float wy = (float)(mt.y >> 16)     * (1.0f / 65535.0f);
    const int x1 = x0 + 1, y1 = y0 + 1;

    const float fy0 = ((unsigned)y0 < HH) ? 1.0f : 0.0f;
    const float fy1 = ((unsigned)y1 < HH) ? 1.0f : 0.0f;
    const float fx0 = ((unsigned)x0 < WW) ? 1.0f : 0.0f;
    const float fx1 = ((unsigned)x1 < WW) ? 1.0f : 0.0f;

    const int xc0 = min(max(x0, 0), WW - 1);
    const int xc1 = min(max(x1, 0), WW - 1);
    const int yc0 = min(max(y0, 0), HH - 1);
    const int yc1 = min(max(y1, 0), HH - 1);

    const float4* __restrict__ vf = (const float4*)vol;
    const int base = b << 16;
    float4 v00 = __ldg(&vf[(base + yc0 * WW + xc0) * 4 + c4]);
    float4 v01 = __ldg(&vf[(base + yc0 * WW + xc1) * 4 + c4]);
    float4 v10 = __ldg(&vf[(base + yc1 * WW + xc0) * 4 + c4]);
    float4 v11 = __ldg(&vf[(base + yc1 * WW + xc1) * 4 + c4]);

    const float w00 = (1.0f - wy) * (1.0f - wx) * (fy0 * fx0);
    const float w01 = (1.0f - wy) * wx          * (fy0 * fx1);
    const float w10 = wy * (1.0f - wx)          * (fy1 * fx0);
    const float w11 = wy * wx                   * (fy1 * fx1);

    float4 r;
    r.x = v00.x * w00 + v01.x * w01 + v10.x * w10 + v11.x * w11;
    r.y = v00.y * w00 + v01.y * w01 + v10.y * w10 + v11.y * w11;
    r.z = v00.z * w00 + v01.z * w01 + v10.z * w10 + v11.z * w11;
    r.w = v00.w * w00 + v01.w * w01 + v10.w * w10 + v11.w * w11;
    ((float4*)out)[idx] = r;
}

// --------------------------- launch ------------------------------------------
extern "C" void kernel_launch(void* const* d_in, const int* in_sizes, int n_in,
                              void* d_out, int out_size) {
    const float* vol        = (const float*)d_in[0];
    const float* cp_offsets = (const float*)d_in[1];
    float* out = (float*)d_out;

    host_build_const();   // pure host math; recorded copy node only
    cudaMemcpyToSymbolAsync(d_c, &h_c, sizeof(h_c), 0,
                            cudaMemcpyHostToDevice, 0);

    tps_apply_kernel<<<(NA * 32 * 32) / 256, 256>>>(cp_offsets);

    // loc: PDL secondary of apply (2 threads/pixel, 512 blocks)
    {
        cudaLaunchConfig_t cfg = {};
        cfg.gridDim  = dim3((HH * WW * 2) / 256);
        cfg.blockDim = dim3(256);
        cudaLaunchAttribute attr[1];
        attr[0].id = cudaLaunchAttributeProgrammaticStreamSerialization;
        attr[0].val.programmaticStreamSerializationAllowed = 1;
        cfg.attrs = attr;
        cfg.numAttrs = 1;
        cudaLaunchKernelEx(&cfg, tps_loc_kernel);
    }

    // sample: PDL secondary of loc
    {
        cudaLaunchConfig_t cfg = {};
        cfg.gridDim  = dim3((BB * HH * WW * 4) / 256);
        cfg.blockDim = dim3(256);
        cudaLaunchAttribute attr[1];
        attr[0].id = cudaLaunchAttributeProgrammaticStreamSerialization;
        attr[0].val.programmaticStreamSerializationAllowed = 1;
        cfg.attrs = attr;
        cfg.numAttrs = 1;
        cudaLaunchKernelEx(&cfg, tps_sample_kernel, vol, out);
    }
}